// round 3
// baseline (speedup 1.0000x reference)
#include <cuda_runtime.h>
#include <math.h>

#define K_DIM   76800           // 3*160*160
#define NGROUP  (K_DIM / 4)     // 19200 groups of 4 columns
#define NBATCH  1024
#define NOUT    8
#define THREADS 768
#define ROWS    2
#define RT      384             // threads per row (12 warps)
#define NITER   (NGROUP / RT)   // 50
#define EPS_F   1e-5f

// ---------------- device scratch ----------------
__device__ double g_mp[256];
__device__ float  g_wscale;               // fl(1/clip(mean|W|,eps))
__device__ float  g_c;                    // tf32(fl(1/g_wscale))
__device__ int    g_wpack[NGROUP * NOUT]; // packed ternary weights (s8 x4)

// ---------------- ptx helpers ----------------
__device__ __forceinline__ float tf32_rna(float x) {
    unsigned u;
    asm("cvt.rna.tf32.f32 %0, %1;" : "=r"(u) : "f"(x));
    return __uint_as_float(u);
}
__device__ __forceinline__ int dp4a_ss(unsigned a, int b, int c) {
    asm("dp4a.s32.s32 %0, %1, %2, %3;" : "=r"(c) : "r"(a), "r"(b), "r"(c));
    return c;
}
__device__ __forceinline__ int dp2a_lo_us(unsigned a, int b, int c) {
    asm("dp2a.lo.u32.s32 %0, %1, %2, %3;" : "=r"(c) : "r"(a), "r"(b), "r"(c));
    return c;
}
__device__ __forceinline__ int dp2a_hi_us(unsigned a, int b, int c) {
    asm("dp2a.hi.u32.s32 %0, %1, %2, %3;" : "=r"(c) : "r"(a), "r"(b), "r"(c));
    return c;
}
__device__ __forceinline__ unsigned prmt(unsigned a, unsigned b, unsigned s) {
    unsigned d;
    asm("prmt.b32 %0, %1, %2, %3;" : "=r"(d) : "r"(a), "r"(b), "r"(s));
    return d;
}

// ---------------- W pipeline ----------------
__global__ void wmean_kernel(const float* __restrict__ W, int n) {
    double s = 0.0;
    for (int i = blockIdx.x * blockDim.x + threadIdx.x; i < n;
         i += gridDim.x * blockDim.x)
        s += (double)fabsf(W[i]);
    __shared__ double sh[256];
    sh[threadIdx.x] = s;
    __syncthreads();
    for (int off = 128; off > 0; off >>= 1) {
        if (threadIdx.x < off) sh[threadIdx.x] += sh[threadIdx.x + off];
        __syncthreads();
    }
    if (threadIdx.x == 0) g_mp[blockIdx.x] = sh[0];
}

__global__ void wfinal_kernel() {
    __shared__ double sh[256];
    sh[threadIdx.x] = g_mp[threadIdx.x];
    __syncthreads();
    for (int off = 128; off > 0; off >>= 1) {
        if (threadIdx.x < off) sh[threadIdx.x] += sh[threadIdx.x + off];
        __syncthreads();
    }
    if (threadIdx.x == 0) {
        float sumf = (float)sh[0];
        float mean = __fdiv_rn(sumf, (float)(NOUT * K_DIM));
        float mcl  = fmaxf(mean, EPS_F);
        float wsc  = __fdiv_rn(1.0f, mcl);
        g_wscale   = wsc;
        float wq1  = __fdiv_rn(1.0f, wsc);
        g_c        = tf32_rna(wq1);
    }
}

__global__ void wpack_kernel(const float* __restrict__ W) {
    int g = blockIdx.x * blockDim.x + threadIdx.x;
    if (g >= NGROUP) return;
    float wscale = g_wscale;
    int col = g * 4;
    #pragma unroll
    for (int o = 0; o < NOUT; o++) {
        const float* wr = W + o * K_DIM + col;
        int p = 0;
        #pragma unroll
        for (int j = 0; j < 4; j++) {
            int t = __float2int_rn(wr[j] * wscale);
            t = max(-1, min(1, t));
            p |= (t & 0xff) << (8 * j);
        }
        g_wpack[g * NOUT + o] = p;
    }
}

// ---------------- main fused kernel ----------------
// dynamic smem: lane-replicated LUT  int lut[2][256][32]  (64KB)
extern __shared__ int s_lut[];

// one-row body: 4 columns x 8 outputs, exact tf32-emulated integer dot
#define BODY(a, wA, wB, sv, lp, aL, aH)                                        \
    do {                                                                       \
        int q0 = __float2int_rn((a).x * (sv));                                 \
        int q1 = __float2int_rn((a).y * (sv));                                 \
        int q2 = __float2int_rn((a).z * (sv));                                 \
        int q3 = __float2int_rn((a).w * (sv));                                 \
        unsigned R0 = (unsigned)(lp)[q0 << 5];                                 \
        unsigned R1 = (unsigned)(lp)[q1 << 5];                                 \
        unsigned R2 = (unsigned)(lp)[q2 << 5];                                 \
        unsigned R3 = (unsigned)(lp)[q3 << 5];                                 \
        unsigned lo = prmt(R0, R1, 0x5410);                                    \
        unsigned hi = prmt(R2, R3, 0x5410);                                    \
        unsigned hp = prmt(prmt(R0, R1, 0x0062), prmt(R2, R3, 0x0062), 0x5410);\
        aL[0] = dp2a_lo_us(lo, (wA).x, aL[0]); aL[0] = dp2a_hi_us(hi, (wA).x, aL[0]); aH[0] = dp4a_ss(hp, (wA).x, aH[0]); \
        aL[1] = dp2a_lo_us(lo, (wA).y, aL[1]); aL[1] = dp2a_hi_us(hi, (wA).y, aL[1]); aH[1] = dp4a_ss(hp, (wA).y, aH[1]); \
        aL[2] = dp2a_lo_us(lo, (wA).z, aL[2]); aL[2] = dp2a_hi_us(hi, (wA).z, aL[2]); aH[2] = dp4a_ss(hp, (wA).z, aH[2]); \
        aL[3] = dp2a_lo_us(lo, (wA).w, aL[3]); aL[3] = dp2a_hi_us(hi, (wA).w, aL[3]); aH[3] = dp4a_ss(hp, (wA).w, aH[3]); \
        aL[4] = dp2a_lo_us(lo, (wB).x, aL[4]); aL[4] = dp2a_hi_us(hi, (wB).x, aL[4]); aH[4] = dp4a_ss(hp, (wB).x, aH[4]); \
        aL[5] = dp2a_lo_us(lo, (wB).y, aL[5]); aL[5] = dp2a_hi_us(hi, (wB).y, aL[5]); aH[5] = dp4a_ss(hp, (wB).y, aH[5]); \
        aL[6] = dp2a_lo_us(lo, (wB).z, aL[6]); aL[6] = dp2a_hi_us(hi, (wB).z, aL[6]); aH[6] = dp4a_ss(hp, (wB).z, aH[6]); \
        aL[7] = dp2a_lo_us(lo, (wB).w, aL[7]); aL[7] = dp2a_hi_us(hi, (wB).w, aL[7]); aH[7] = dp4a_ss(hp, (wB).w, aH[7]); \
    } while (0)

__global__ void __launch_bounds__(THREADS, 1)
main_kernel(const float* __restrict__ x, float* __restrict__ out) {
    __shared__ float s_wmax[THREADS / 32];
    __shared__ float s_scale[ROWS];
    __shared__ int   s_gexp[ROWS];
    __shared__ unsigned long long s_acc[ROWS * NOUT];

    const int tid = threadIdx.x;
    const int wid = tid >> 5, lid = tid & 31;
    const int row = (wid >= 12);                 // warps 0-11: row0, 12-23: row1
    const int rtid = (wid - row * 12) * 32 + lid; // 0..383 within row group
    const int row0 = blockIdx.x * ROWS;

    const float4* __restrict__ xr =
        (const float4*)(x + (size_t)(row0 + row) * K_DIM);

    // ---- pass 1: this half scans its own row for max|x| ----
    float m = 0.f;
    #pragma unroll 5
    for (int i = 0; i < NITER; i++) {
        float4 v = xr[rtid + i * RT];
        m = fmaxf(m, fmaxf(fmaxf(fabsf(v.x), fabsf(v.y)),
                           fmaxf(fabsf(v.z), fabsf(v.w))));
    }
    #pragma unroll
    for (int off = 16; off > 0; off >>= 1)
        m = fmaxf(m, __shfl_xor_sync(0xffffffffu, m, off));
    if (lid == 0) s_wmax[wid] = m;
    if (tid < ROWS * NOUT) s_acc[tid] = 0ull;
    __syncthreads();
    if (tid < ROWS) {
        float mm = s_wmax[tid * 12];
        #pragma unroll
        for (int i = 1; i < 12; i++) mm = fmaxf(mm, s_wmax[tid * 12 + i]);
        s_scale[tid] = __fdiv_rn(127.0f, fmaxf(mm, EPS_F));  // == reference
    }
    __syncthreads();
    const float sv = s_scale[row];

    // ---- build per-row tf32 LUT: R[q] = tf32(fl(q/scale)) / 2^gexp ----
    for (int e = tid; e < 2 * 256; e += THREADS) {
        int r  = e >> 8;
        int qb = e & 255;               // q = qb - 128
        int q  = qb - 128;
        float s = s_scale[r];
        float t1 = tf32_rna(__fdiv_rn(1.0f, s));
        int gexp = ilogbf(t1) - 10;
        int R = 0;
        if (q != -128) {
            float rr = __fdiv_rn((float)q, s);
            float t  = tf32_rna(rr);
            R = __float2int_rn(ldexpf(t, -gexp));
        }
        if (qb == 129) s_gexp[r] = gexp;
        int* dst = s_lut + r * 8192 + qb * 32;
        #pragma unroll
        for (int l = 0; l < 32; l++) dst[l] = R;  // lane-replicated: no conflicts
    }
    __syncthreads();

    // ---- pass 2: software-pipelined quant + LUT + dp2a/dp4a dot ----
    int aL[NOUT] = {0,0,0,0,0,0,0,0};
    int aH[NOUT] = {0,0,0,0,0,0,0,0};
    const int4* __restrict__ wp = (const int4*)g_wpack;
    const int* __restrict__ lp = s_lut + row * 8192 + 4096 + lid; // +128 bias folded

    float4 a  = xr[rtid];
    int4   wA = wp[2 * rtid];
    int4   wB = wp[2 * rtid + 1];
    for (int i = 1; i < NITER; i++) {
        const int gn = rtid + i * RT;
        float4 an  = xr[gn];             // prefetch next (L2-resident)
        int4   wAn = wp[2 * gn];
        int4   wBn = wp[2 * gn + 1];
        BODY(a, wA, wB, sv, lp, aL, aH);
        a = an; wA = wAn; wB = wBn;
    }
    BODY(a, wA, wB, sv, lp, aL, aH);

    // ---- exact integer reduction ----
    #pragma unroll
    for (int o = 0; o < NOUT; o++) {
        int L = __reduce_add_sync(0xffffffffu, aL[o]);
        int H = __reduce_add_sync(0xffffffffu, aH[o]);
        if (lid == 0) {
            long long v = (long long)H * 65536ll + (long long)L;
            atomicAdd(&s_acc[row * NOUT + o], (unsigned long long)v);
        }
    }
    __syncthreads();

    // ---- softmax (exact tf32-emulated logits) ----
    if (tid < ROWS) {
        float fs = ldexpf(1.0f, s_gexp[tid]);
        float c  = g_c;
        float y[NOUT];
        float mx = -3.0e38f;
        #pragma unroll
        for (int o = 0; o < NOUT; o++) {
            long long S = (long long)s_acc[tid * NOUT + o];
            y[o] = ((float)S * fs) * c;
            mx = fmaxf(mx, y[o]);
        }
        float se = 0.f;
        #pragma unroll
        for (int o = 0; o < NOUT; o++) {
            y[o] = expf(y[o] - mx);
            se += y[o];
        }
        float inv = 1.0f / se;
        #pragma unroll
        for (int o = 0; o < NOUT; o++)
            out[(size_t)(row0 + tid) * NOUT + o] = y[o] * inv;
    }
}

// ---------------- launch ----------------
extern "C" void kernel_launch(void* const* d_in, const int* in_sizes, int n_in,
                              void* d_out, int out_size) {
    const float* x = (const float*)d_in[0];
    const float* W = (const float*)d_in[1];
    if (n_in >= 2 && in_sizes[0] == NOUT * K_DIM && in_sizes[1] == NBATCH * K_DIM) {
        x = (const float*)d_in[1];
        W = (const float*)d_in[0];
    }
    float* out = (float*)d_out;

    // 64KB dynamic smem = LUT only; registers (>42/thread) enforce 1 CTA/SM.
    // Small carveout request -> large L1 for W sharing between row-half warps.
    cudaFuncSetAttribute(main_kernel,
                         cudaFuncAttributeMaxDynamicSharedMemorySize, 66 * 1024);
    cudaFuncSetAttribute(main_kernel,
                         cudaFuncAttributePreferredSharedMemoryCarveout, 33);

    wmean_kernel<<<256, 256>>>(W, NOUT * K_DIM);
    wfinal_kernel<<<1, 256>>>();
    wpack_kernel<<<(NGROUP + 255) / 256, 256>>>(W);
    main_kernel<<<NBATCH / ROWS, THREADS, 64 * 1024>>>(x, out);
}